// round 13
// baseline (speedup 1.0000x reference)
#include <cuda_runtime.h>

// B=256, N=1024, D=512, K=2.
// out[row][k] = softmax_k( exp(logit_scale) * dot(x[row], tf[k]/||tf[k]||) )
// rows = 262144. Persistent 592-block kernel (1 wave, static split),
// warp-per-row grid-stride. K=2 softmax folded into a single sigmoid,
// streaming loads (__ldcs) and stores (__stcs).
// Measured: 81.9us kernel, 6612 GB/s (82.6% of spec) — at the HBM wall;
// model closes to ~100% (514MiB / 6612GB/s = 81.5us).

#define D 512
#define ROWS (256 * 1024)
#define GRID 592
#define TPB 256
#define NWARP ((GRID * TPB) / 32)   // 4736 warps
#define ITERS (ROWS / NWARP)        // ROWS % NWARP != 0 handled below

__global__ __launch_bounds__(TPB, 4)
void prompts_kernel(const float4* __restrict__ x,
                    const float4* __restrict__ tf,   // [2*512] floats as float4
                    const float*  __restrict__ ls,
                    float2* __restrict__ out) {
    const int lane = threadIdx.x & 31;
    const int warp = (blockIdx.x * TPB + threadIdx.x) >> 5;
    const unsigned FULL = 0xffffffffu;

    // ---- per-warp weight setup: load tf, normalize, fold exp(logit_scale) ----
    float4 w0[4], w1[4];
    float n0 = 0.f, n1 = 0.f;
    #pragma unroll
    for (int p = 0; p < 4; p++) {
        w0[p] = tf[p * 32 + lane];           // prompt 0: floats [0,512)
        w1[p] = tf[128 + p * 32 + lane];     // prompt 1: floats [512,1024)
        n0 += w0[p].x * w0[p].x + w0[p].y * w0[p].y + w0[p].z * w0[p].z + w0[p].w * w0[p].w;
        n1 += w1[p].x * w1[p].x + w1[p].y * w1[p].y + w1[p].z * w1[p].z + w1[p].w * w1[p].w;
    }
    #pragma unroll
    for (int o = 16; o; o >>= 1) {
        n0 += __shfl_xor_sync(FULL, n0, o);
        n1 += __shfl_xor_sync(FULL, n1, o);
    }
    const float scale = __expf(ls[0]);
    const float c0 = rsqrtf(n0) * scale;
    const float c1 = rsqrtf(n1) * scale;
    #pragma unroll
    for (int p = 0; p < 4; p++) {
        w0[p].x *= c0; w0[p].y *= c0; w0[p].z *= c0; w0[p].w *= c0;
        w1[p].x *= c1; w1[p].y *= c1; w1[p].z *= c1; w1[p].w *= c1;
    }

    // ---- main loop: warp-per-row, pointer increment, down-counted trip count ----
    // ROWS = 262144, NWARP = 4736 -> 55 full iterations + remainder 1664 warps
    // do a 56th row. niter is uniform per warp.
    int niter = ROWS / NWARP + ((warp < (ROWS % NWARP)) ? 1 : 0);
    const float4* xr = x + (size_t)warp * (D / 4) + lane;
    const size_t step = (size_t)NWARP * (D / 4);
    int r = warp;

    for (; niter > 0; --niter, r += NWARP, xr += step) {
        float s0 = 0.f, s1 = 0.f;
        #pragma unroll
        for (int p = 0; p < 4; p++) {
            float4 v = __ldcs(xr + p * 32);
            s0 = fmaf(v.x, w0[p].x, s0);
            s0 = fmaf(v.y, w0[p].y, s0);
            s0 = fmaf(v.z, w0[p].z, s0);
            s0 = fmaf(v.w, w0[p].w, s0);
            s1 = fmaf(v.x, w1[p].x, s1);
            s1 = fmaf(v.y, w1[p].y, s1);
            s1 = fmaf(v.z, w1[p].z, s1);
            s1 = fmaf(v.w, w1[p].w, s1);
        }
        #pragma unroll
        for (int o = 16; o; o >>= 1) {
            s0 += __shfl_xor_sync(FULL, s0, o);
            s1 += __shfl_xor_sync(FULL, s1, o);
        }
        if (lane == 0) {
            // K=2 softmax == sigmoid of the logit difference.
            float d  = s1 - s0;
            float e  = __expf(d);
            float p0 = __fdividef(1.f, 1.f + e);
            float p1 = 1.f - p0;
            __stcs(out + r, make_float2(p0, p1));
        }
    }
}

extern "C" void kernel_launch(void* const* d_in, const int* in_sizes, int n_in,
                              void* d_out, int out_size) {
    const float* x  = (const float*)d_in[0];   // [256,1024,512] f32
    const float* tf = (const float*)d_in[1];   // [2,512] f32
    const float* ls = (const float*)d_in[2];   // [1] f32
    float2* out = (float2*)d_out;              // [262144,2] f32

    prompts_kernel<<<GRID, TPB>>>((const float4*)x, (const float4*)tf, ls, out);
}